// round 4
// baseline (speedup 1.0000x reference)
#include <cuda_runtime.h>
#include <cuda_fp16.h>
#include <cstdint>

#define NN   50000
#define EE   800000
#define KIN  256
#define FOUT 128
#define NEG_ATT 0.2f
#define NEG_ACT 0.01f
#define BN_EPS  1e-5f

// Scratch (static device arrays — no allocations allowed)
__device__ __align__(16) float   g_h[(size_t)NN * FOUT];   // projected features fp32
__device__ __align__(16) __half2 g_hh[(size_t)NN * 64];    // fp16 copy for edge gather
__device__ __align__(16) float   g_s[NN * 4];              // a_src per node/head
__device__ __align__(16) float   g_d[NN * 4];              // a_dst per node/head
__device__ __align__(16) float   g_stats[256];             // col sum[128], sumsq[128]
__device__ int g_deg[NN];                                  // in-degree histogram
__device__ int g_off[NN + 1];                              // CSR offsets
__device__ int g_cur[NN];                                  // scatter cursors
__device__ int g_srcs[EE];                                 // CSR: src per slot

// ---------------------------------------------------------------------------
// Kernel 1: h = x @ W^T  (64x128 tile, BK=32, 4x8 reg tile). Epilogue writes
// fp32 h AND an fp16 copy used by the edge-gather kernel.
// ---------------------------------------------------------------------------
__global__ __launch_bounds__(256) void gemm_k(const float* __restrict__ x,
                                              const float* __restrict__ W) {
    __shared__ float As[32][68];
    __shared__ float Bs[32][128];
    const int row0 = blockIdx.x * 64;
    const int tid  = threadIdx.x;
    const int tr   = tid >> 4;
    const int tc   = tid & 15;

    float acc[4][8];
#pragma unroll
    for (int i = 0; i < 4; i++)
#pragma unroll
        for (int j = 0; j < 8; j++) acc[i][j] = 0.f;

    for (int k0 = 0; k0 < KIN; k0 += 32) {
#pragma unroll
        for (int i = 0; i < 2; i++) {
            int f = tid * 2 + i;
            int r = f >> 3, kk = (f & 7) << 2;
            int gr = row0 + r;
            float4 v = make_float4(0.f, 0.f, 0.f, 0.f);
            if (gr < NN) v = *(const float4*)(x + (size_t)gr * KIN + k0 + kk);
            As[kk + 0][r] = v.x; As[kk + 1][r] = v.y;
            As[kk + 2][r] = v.z; As[kk + 3][r] = v.w;
        }
#pragma unroll
        for (int i = 0; i < 4; i++) {
            int f = tid * 4 + i;
            int j = f >> 3, kk = (f & 7) << 2;
            float4 v = *(const float4*)(W + (size_t)j * KIN + k0 + kk);
            Bs[kk + 0][j] = v.x; Bs[kk + 1][j] = v.y;
            Bs[kk + 2][j] = v.z; Bs[kk + 3][j] = v.w;
        }
        __syncthreads();
#pragma unroll
        for (int k = 0; k < 32; k++) {
            float4 a  = *(const float4*)&As[k][tr * 4];
            float4 b0 = *(const float4*)&Bs[k][tc * 8];
            float4 b1 = *(const float4*)&Bs[k][tc * 8 + 4];
            float av[4] = {a.x, a.y, a.z, a.w};
            float bv[8] = {b0.x, b0.y, b0.z, b0.w, b1.x, b1.y, b1.z, b1.w};
#pragma unroll
            for (int i = 0; i < 4; i++)
#pragma unroll
                for (int j = 0; j < 8; j++) acc[i][j] += av[i] * bv[j];
        }
        __syncthreads();
    }
#pragma unroll
    for (int i = 0; i < 4; i++) {
        int gr = row0 + tr * 4 + i;
        if (gr < NN) {
            float* p = g_h + (size_t)gr * FOUT + tc * 8;
            *(float4*)(p)     = make_float4(acc[i][0], acc[i][1], acc[i][2], acc[i][3]);
            *(float4*)(p + 4) = make_float4(acc[i][4], acc[i][5], acc[i][6], acc[i][7]);
            __half2 hh[4];
            hh[0] = __floats2half2_rn(acc[i][0], acc[i][1]);
            hh[1] = __floats2half2_rn(acc[i][2], acc[i][3]);
            hh[2] = __floats2half2_rn(acc[i][4], acc[i][5]);
            hh[3] = __floats2half2_rn(acc[i][6], acc[i][7]);
            *(uint4*)(g_hh + (size_t)gr * 64 + tc * 4) = *(uint4*)hh;
        }
    }
}

// ---------------------------------------------------------------------------
// Kernel 2: per-node attention scores. One warp per node. Also zeroes the
// BN stats (block 0) and the degree histogram (first NN global threads).
// ---------------------------------------------------------------------------
__global__ __launch_bounds__(256) void node_score_k(const float* __restrict__ att_src,
                                                    const float* __restrict__ att_dst) {
    if (blockIdx.x == 0) g_stats[threadIdx.x] = 0.f;
    int gtid = blockIdx.x * blockDim.x + threadIdx.x;
    if (gtid < NN) g_deg[gtid] = 0;

    int warp = gtid >> 5;
    int lane = threadIdx.x & 31;
    if (warp >= NN) return;
    int head = lane >> 3, sub = lane & 7;

    float4 hv  = *(const float4*)(g_h + (size_t)warp * FOUT + lane * 4);
    float4 as4 = *(const float4*)(att_src + head * 32 + sub * 4);
    float4 ad4 = *(const float4*)(att_dst + head * 32 + sub * 4);
    float ps = hv.x * as4.x + hv.y * as4.y + hv.z * as4.z + hv.w * as4.w;
    float pd = hv.x * ad4.x + hv.y * ad4.y + hv.z * ad4.z + hv.w * ad4.w;
#pragma unroll
    for (int o = 4; o; o >>= 1) {
        ps += __shfl_xor_sync(0xFFFFFFFFu, ps, o);
        pd += __shfl_xor_sync(0xFFFFFFFFu, pd, o);
    }
    if (sub == 0) {
        g_s[warp * 4 + head] = ps;
        g_d[warp * 4 + head] = pd;
    }
}

// ---------------------------------------------------------------------------
// Kernel 3: degree histogram over dst.
// ---------------------------------------------------------------------------
__global__ __launch_bounds__(256) void hist_k(const int* __restrict__ ei) {
    int e = blockIdx.x * blockDim.x + threadIdx.x;
    if (e < EE) atomicAdd(&g_deg[ei[EE + e]], 1);
}

// ---------------------------------------------------------------------------
// Kernel 4: single-block exclusive scan of degrees -> offsets + cursors.
// ---------------------------------------------------------------------------
__global__ __launch_bounds__(1024) void scan_k() {
    __shared__ int csum[1024];
    const int t = threadIdx.x;
    const int CH = (NN + 1023) / 1024;          // 49
    int lo = t * CH, hi = min(lo + CH, NN);
    int s = 0;
    for (int i = lo; i < hi; i++) s += g_deg[i];
    csum[t] = s;
    __syncthreads();
    for (int off = 1; off < 1024; off <<= 1) {
        int v = (t >= off) ? csum[t - off] : 0;
        __syncthreads();
        csum[t] += v;
        __syncthreads();
    }
    int base = csum[t] - s;                     // exclusive prefix
    for (int i = lo; i < hi; i++) {
        g_off[i] = base;
        g_cur[i] = base;
        base += g_deg[i];
    }
    if (t == 1023) g_off[NN] = EE;
}

// ---------------------------------------------------------------------------
// Kernel 5: scatter edges into CSR slots.
// ---------------------------------------------------------------------------
__global__ __launch_bounds__(256) void scatter_k(const int* __restrict__ ei) {
    int e = blockIdx.x * blockDim.x + threadIdx.x;
    if (e >= EE) return;
    int dst = ei[EE + e];
    int pos = atomicAdd(&g_cur[dst], 1);
    g_srcs[pos] = ei[e];
}

// ---------------------------------------------------------------------------
// Kernel 6: per-node gather-aggregate. One warp per dst node.
// Self-loop init, then walk CSR in-edges: w = exp(lrelu(s[src]+d[n])),
// num += w * h16[src], den += w. Write y = num/den + bias.
// ---------------------------------------------------------------------------
__global__ __launch_bounds__(256) void agg_k(const float* __restrict__ bias,
                                             float* __restrict__ out) {
    int n = (blockIdx.x * blockDim.x + threadIdx.x) >> 5;
    int lane = threadIdx.x & 31;
    if (n >= NN) return;
    const int head = lane >> 3;

    const float d_n = g_d[n * 4 + head];
    float e0 = g_s[n * 4 + head] + d_n;
    e0 = e0 < 0.f ? NEG_ATT * e0 : e0;
    float w = __expf(e0);

    float4 hs = *(const float4*)(g_h + (size_t)n * FOUT + lane * 4);
    float a0 = w * hs.x, a1 = w * hs.y, a2 = w * hs.z, a3 = w * hs.w;
    float den = w;

    const uint2* __restrict__ hh = (const uint2*)g_hh;   // 4 halfs per entry
    int i = g_off[n];
    const int end = g_off[n + 1];

    for (; i + 2 <= end; i += 2) {
        int s0 = g_srcs[i], s1 = g_srcs[i + 1];
        float sv0 = g_s[s0 * 4 + head];
        float sv1 = g_s[s1 * 4 + head];
        uint2 p0 = hh[(size_t)s0 * 32 + lane];
        uint2 p1 = hh[(size_t)s1 * 32 + lane];
        float ea = sv0 + d_n; ea = ea < 0.f ? NEG_ATT * ea : ea;
        float eb = sv1 + d_n; eb = eb < 0.f ? NEG_ATT * eb : eb;
        float w0 = __expf(ea), w1 = __expf(eb);
        den += w0 + w1;
        float2 l0 = __half22float2(*(__half2*)&p0.x);
        float2 u0 = __half22float2(*(__half2*)&p0.y);
        float2 l1 = __half22float2(*(__half2*)&p1.x);
        float2 u1 = __half22float2(*(__half2*)&p1.y);
        a0 = fmaf(w0, l0.x, fmaf(w1, l1.x, a0));
        a1 = fmaf(w0, l0.y, fmaf(w1, l1.y, a1));
        a2 = fmaf(w0, u0.x, fmaf(w1, u1.x, a2));
        a3 = fmaf(w0, u0.y, fmaf(w1, u1.y, a3));
    }
    if (i < end) {
        int s0 = g_srcs[i];
        float sv0 = g_s[s0 * 4 + head];
        uint2 p0 = hh[(size_t)s0 * 32 + lane];
        float ea = sv0 + d_n; ea = ea < 0.f ? NEG_ATT * ea : ea;
        float w0 = __expf(ea);
        den += w0;
        float2 l0 = __half22float2(*(__half2*)&p0.x);
        float2 u0 = __half22float2(*(__half2*)&p0.y);
        a0 = fmaf(w0, l0.x, a0); a1 = fmaf(w0, l0.y, a1);
        a2 = fmaf(w0, u0.x, a2); a3 = fmaf(w0, u0.y, a3);
    }

    float rinv = 1.0f / den;
    float4 b4 = *(const float4*)(bias + lane * 4);
    *(float4*)(out + (size_t)n * FOUT + lane * 4) =
        make_float4(fmaf(a0, rinv, b4.x), fmaf(a1, rinv, b4.y),
                    fmaf(a2, rinv, b4.z), fmaf(a3, rinv, b4.w));
}

// ---------------------------------------------------------------------------
// Kernel 7: column sum / sumsq of y (already includes bias). float4 per thread.
// ---------------------------------------------------------------------------
__global__ __launch_bounds__(256) void stats_k(const float* __restrict__ out) {
    const int t = threadIdx.x;
    const int cg = t & 31;          // column quad
    const int rw = t >> 5;          // 0..7 row within block slice
    float s[4] = {0.f, 0.f, 0.f, 0.f}, q[4] = {0.f, 0.f, 0.f, 0.f};
    for (int r = blockIdx.x * 8 + rw; r < NN; r += gridDim.x * 8) {
        float4 v = *(const float4*)(out + (size_t)r * FOUT + cg * 4);
        s[0] += v.x; q[0] = fmaf(v.x, v.x, q[0]);
        s[1] += v.y; q[1] = fmaf(v.y, v.y, q[1]);
        s[2] += v.z; q[2] = fmaf(v.z, v.z, q[2]);
        s[3] += v.w; q[3] = fmaf(v.w, v.w, q[3]);
    }
#pragma unroll
    for (int j = 0; j < 4; j++) {
        atomicAdd(&g_stats[cg * 4 + j], s[j]);
        atomicAdd(&g_stats[128 + cg * 4 + j], q[j]);
    }
}

// ---------------------------------------------------------------------------
// Kernel 8: finalize — BN + LeakyReLU(0.01), float4 in place.
// ---------------------------------------------------------------------------
__global__ __launch_bounds__(256) void final_k(float* __restrict__ out,
                                               const float* __restrict__ gamma,
                                               const float* __restrict__ beta) {
    size_t idx = (size_t)blockIdx.x * blockDim.x + threadIdx.x;   // N*32 quads
    if (idx >= (size_t)NN * 32) return;
    int c = (int)(idx & 31) * 4;
    size_t r = idx >> 5;
    float4 v = *(float4*)(out + r * FOUT + c);
    const float invN = 1.0f / NN;
    float y[4] = {v.x, v.y, v.z, v.w};
#pragma unroll
    for (int j = 0; j < 4; j++) {
        int cc = c + j;
        float mu  = g_stats[cc] * invN;
        float var = fmaf(g_stats[128 + cc], invN, -mu * mu);
        float z = (y[j] - mu) * rsqrtf(var + BN_EPS) * gamma[cc] + beta[cc];
        y[j] = z < 0.f ? NEG_ACT * z : z;
    }
    *(float4*)(out + r * FOUT + c) = make_float4(y[0], y[1], y[2], y[3]);
}

// ---------------------------------------------------------------------------
extern "C" void kernel_launch(void* const* d_in, const int* in_sizes, int n_in,
                              void* d_out, int out_size) {
    const float* x       = (const float*)d_in[0];
    const int*   ei      = (const int*)  d_in[1];
    const float* W       = (const float*)d_in[2];
    const float* att_src = (const float*)d_in[3];
    const float* att_dst = (const float*)d_in[4];
    const float* bias    = (const float*)d_in[5];
    const float* gamma   = (const float*)d_in[6];
    const float* beta    = (const float*)d_in[7];
    float* out = (float*)d_out;

    gemm_k<<<(NN + 63) / 64, 256>>>(x, W);
    node_score_k<<<(NN * 32 + 255) / 256, 256>>>(att_src, att_dst);
    hist_k<<<(EE + 255) / 256, 256>>>(ei);
    scan_k<<<1, 1024>>>();
    scatter_k<<<(EE + 255) / 256, 256>>>(ei);
    agg_k<<<(NN * 32 + 255) / 256, 256>>>(bias, out);
    stats_k<<<512, 256>>>(out);
    final_k<<<(int)(((size_t)NN * 32 + 255) / 256), 256>>>(out, gamma, beta);
}